// round 2
// baseline (speedup 1.0000x reference)
#include <cuda_runtime.h>
#include <cstdint>

// Problem constants
constexpr int BATCH = 2048;
constexpr int DIM   = 1024;
constexpr int MOL   = 8;
constexpr int NPAIR = 28;
constexpr int LQ    = 36;   // MOL + NPAIR
constexpr int OUTD  = 4;

// triu_indices(8,1) in combinations order
__constant__ int c_pi[NPAIR] = {0,0,0,0,0,0,0,1,1,1,1,1,1,2,2,2,2,2,3,3,3,3,4,4,4,5,5,6};
__constant__ int c_pj[NPAIR] = {1,2,3,4,5,6,7,2,3,4,5,6,7,3,4,5,6,7,4,5,6,7,5,6,7,6,7,7};

// Scratch (static device arrays: allocation-free rule)
__device__ float g_WkT[DIM * DIM];                       // 4 MB  : Wk^T
__device__ float g_G[DIM * DIM];                         // 4 MB  : Wq @ Wk^T
__device__ float g_Z[2ull * BATCH * MOL * DIM];          // 128 MB: [PG ; RG]
__device__ float g_w[2 * BATCH * MOL];                   // effective pooling weights

// ---------------------------------------------------------------------------
// packed f32x2 helpers (Blackwell FFMA2 path)
// ---------------------------------------------------------------------------
__device__ __forceinline__ void ffma2(unsigned long long& c,
                                      unsigned long long a,
                                      unsigned long long b) {
    asm("fma.rn.f32x2 %0, %1, %2, %0;" : "+l"(c) : "l"(a), "l"(b));
}
__device__ __forceinline__ unsigned long long dup2(float a) {
    unsigned long long r;
    asm("mov.b64 %0, {%1, %1};" : "=l"(r) : "f"(a));
    return r;
}
__device__ __forceinline__ float lo32(unsigned long long v) {
    return __uint_as_float((unsigned)v);
}
__device__ __forceinline__ float hi32(unsigned long long v) {
    return __uint_as_float((unsigned)(v >> 32));
}

// ---------------------------------------------------------------------------
// Transpose Wk -> g_WkT   (WkT[k][e] = Wk[e][k])
// ---------------------------------------------------------------------------
__global__ void transpose_kernel(const float* __restrict__ src) {
    __shared__ float tile[32][33];
    int tx = threadIdx.x, ty = threadIdx.y;
    int x = blockIdx.x * 32 + tx;
    int y0 = blockIdx.y * 32;
#pragma unroll
    for (int i = ty; i < 32; i += 8)
        tile[i][tx] = src[(size_t)(y0 + i) * DIM + x];
    __syncthreads();
    int x2 = y0 + tx;
#pragma unroll
    for (int i = ty; i < 32; i += 8)
        g_WkT[(size_t)(blockIdx.x * 32 + i) * DIM + x2] = tile[tx][i];
}

// ---------------------------------------------------------------------------
// Tiled NN GEMM (fp32, f32x2 inner product), 128x128x16 tiles, 256 thr, 8x8/thr
//   mode 0: C=g_G   = A(Wq, row-major 1024x1024) @ g_WkT
//   mode 1: C=g_Z   = X @ g_G, X rows gathered:
//           row = s*16384 + b*8 + m ; s==0 -> p_feats[m,b,:], s==1 -> r_feats[m,b,:]
// ---------------------------------------------------------------------------
#define BM 128
#define BN 128
#define BK 16

__global__ void __launch_bounds__(256) gemm_kernel(
    const float* __restrict__ A, int mode,
    const float* __restrict__ src_p, const float* __restrict__ src_r)
{
    __shared__ float As[BK][BM];
    __shared__ float Bs[BK][BN];

    const float* Bmat = mode ? g_G : g_WkT;
    float*       C    = mode ? g_Z : g_G;

    const int tid = threadIdx.x;
    const int tx = tid & 15;      // col group 0..15
    const int ty = tid >> 4;      // row group 0..15
    const int rowBase = blockIdx.x * BM;
    const int colBase = blockIdx.y * BN;

    // per-thread A load assignment (fixed row)
    const int arow = tid >> 1;           // 0..127
    const int acol = (tid & 1) * 8;      // 0 or 8
    const float* aPtr;
    {
        int gr = rowBase + arow;
        if (mode) {
            int s = gr >> 14;
            int b = (gr >> 3) & (BATCH - 1);
            int m = gr & 7;
            const float* src = s ? src_r : src_p;
            aPtr = src + ((size_t)m * BATCH + b) * DIM;
        } else {
            aPtr = A + (size_t)gr * DIM;
        }
    }
    const int brow = tid >> 4;           // 0..15
    const int bcol = (tid & 15) * 8;     // 0..120

    unsigned long long acc[8][4];
#pragma unroll
    for (int i = 0; i < 8; i++)
#pragma unroll
        for (int j = 0; j < 4; j++) acc[i][j] = 0ull;

    for (int k0 = 0; k0 < DIM; k0 += BK) {
        float4 a0 = *(const float4*)(aPtr + k0 + acol);
        float4 a1 = *(const float4*)(aPtr + k0 + acol + 4);
        const float* bp = Bmat + (size_t)(k0 + brow) * DIM + colBase + bcol;
        float4 b0 = *(const float4*)bp;
        float4 b1 = *(const float4*)(bp + 4);

        __syncthreads();
        As[acol + 0][arow] = a0.x; As[acol + 1][arow] = a0.y;
        As[acol + 2][arow] = a0.z; As[acol + 3][arow] = a0.w;
        As[acol + 4][arow] = a1.x; As[acol + 5][arow] = a1.y;
        As[acol + 6][arow] = a1.z; As[acol + 7][arow] = a1.w;
        *(float4*)&Bs[brow][bcol]     = b0;
        *(float4*)&Bs[brow][bcol + 4] = b1;
        __syncthreads();

#pragma unroll
        for (int kk = 0; kk < BK; kk++) {
            float4 af0 = *(const float4*)&As[kk][ty * 8];
            float4 af1 = *(const float4*)&As[kk][ty * 8 + 4];
            union { float4 f; unsigned long long u[2]; } B0, B1;
            B0.f = *(const float4*)&Bs[kk][tx * 8];
            B1.f = *(const float4*)&Bs[kk][tx * 8 + 4];
            float av[8] = {af0.x, af0.y, af0.z, af0.w, af1.x, af1.y, af1.z, af1.w};
#pragma unroll
            for (int i = 0; i < 8; i++) {
                unsigned long long aa = dup2(av[i]);
                ffma2(acc[i][0], aa, B0.u[0]);
                ffma2(acc[i][1], aa, B0.u[1]);
                ffma2(acc[i][2], aa, B1.u[0]);
                ffma2(acc[i][3], aa, B1.u[1]);
            }
        }
    }

#pragma unroll
    for (int i = 0; i < 8; i++) {
        float4 o0, o1;
        o0.x = lo32(acc[i][0]); o0.y = hi32(acc[i][0]);
        o0.z = lo32(acc[i][1]); o0.w = hi32(acc[i][1]);
        o1.x = lo32(acc[i][2]); o1.y = hi32(acc[i][2]);
        o1.z = lo32(acc[i][3]); o1.w = hi32(acc[i][3]);
        size_t crow = (size_t)(rowBase + ty * 8 + i);
        *(float4*)&C[crow * DIM + colBase + tx * 8]     = o0;
        *(float4*)&C[crow * DIM + colBase + tx * 8 + 4] = o1;
    }
}

// ---------------------------------------------------------------------------
// Per-batch attention: 8x8 grams -> 36x36 expand -> softmax -> mean -> att, w
//   side 0: S_r = PG . R^T  -> att_reactant   (queries=p, keys=r)
//   side 1: S_p = RG . P^T  -> att_product
// ---------------------------------------------------------------------------
__global__ void __launch_bounds__(128) att_kernel(
    const float* __restrict__ r_feats, const float* __restrict__ p_feats,
    float* __restrict__ d_out)
{
    const int b = blockIdx.x;
    const int t = threadIdx.x;

    __shared__ float sS[2][MOL][MOL];
    __shared__ float sProb[2][LQ][LQ];   // 10.4 KB
    __shared__ float sAtt[2][LQ];

    // ---- phase 1: 8x8 grams (128 threads = 2 sides x 64 entries) ----
    {
        int side = t >> 6;
        int q = (t >> 3) & 7;
        int k = t & 7;
        const float* zrow = g_Z + (((size_t)side * BATCH + b) * MOL + q) * DIM;
        const float* feats = side ? p_feats : r_feats;
        const float* frow = feats + ((size_t)k * BATCH + b) * DIM;
        float acc0 = 0.f, acc1 = 0.f;
        for (int d = 0; d < DIM; d += 8) {
            float4 z0 = *(const float4*)(zrow + d);
            float4 f0 = *(const float4*)(frow + d);
            float4 z1 = *(const float4*)(zrow + d + 4);
            float4 f1 = *(const float4*)(frow + d + 4);
            acc0 += z0.x * f0.x + z0.y * f0.y + z0.z * f0.z + z0.w * f0.w;
            acc1 += z1.x * f1.x + z1.y * f1.y + z1.z * f1.z + z1.w * f1.w;
        }
        sS[side][q][k] = acc0 + acc1;
    }
    __syncthreads();

    // ---- phase 2: expand to 36x36 rows, softmax over k, store probs ----
    if (t < 2 * LQ) {
        int side = t / LQ;
        int q = t % LQ;
        int qi, qj;
        if (q < MOL) { qi = q; qj = -1; }
        else         { qi = c_pi[q - MOL]; qj = c_pj[q - MOL]; }

        float row[LQ];
        float maxv = -1e30f;
#pragma unroll
        for (int k = 0; k < LQ; k++) {
            int ki, kj;
            if (k < MOL) { ki = k; kj = -1; }
            else         { ki = c_pi[k - MOL]; kj = c_pj[k - MOL]; }
            float v = sS[side][qi][ki];
            if (kj >= 0) v += sS[side][qi][kj];
            if (qj >= 0) {
                v += sS[side][qj][ki];
                if (kj >= 0) v += sS[side][qj][kj];
            }
            v *= 0.03125f;   // 1/sqrt(1024)
            row[k] = v;
            maxv = fmaxf(maxv, v);
        }
        float sum = 0.f;
#pragma unroll
        for (int k = 0; k < LQ; k++) { row[k] = expf(row[k] - maxv); sum += row[k]; }
        float inv = 1.f / sum;
#pragma unroll
        for (int k = 0; k < LQ; k++) sProb[side][q][k] = row[k] * inv;
    }
    __syncthreads();

    // ---- phase 3: mean over queries -> att, write outputs ----
    if (t < 2 * LQ) {
        int side = t / LQ;
        int k = t % LQ;
        float a = 0.f;
#pragma unroll
        for (int q = 0; q < LQ; q++) a += sProb[side][q][k];
        a *= (1.0f / LQ);
        sAtt[side][k] = a;
        // layout: [out (B*4)] [att_reactant (B*36)] [att_product (B*36)]
        d_out[BATCH * OUTD + side * (BATCH * LQ) + b * LQ + k] = a;
    }
    __syncthreads();

    // ---- phase 4: collapse to 8 effective pooling weights per side ----
    if (t < 16) {
        int side = t >> 3;
        int m = t & 7;
        float w = sAtt[side][m];
#pragma unroll
        for (int pp = 0; pp < NPAIR; pp++)
            if (c_pi[pp] == m || c_pj[pp] == m) w += sAtt[side][MOL + pp];
        g_w[side * BATCH * MOL + b * MOL + m] = w;
    }
}

// ---------------------------------------------------------------------------
// Pooling + prediction head (fused): reads the 4 big tensors once.
//   reaction[b,d] = sum_m wr[m]*(r+rn)[m,b,d] - wp[m]*(p+pn)[m,b,d]
//   out[b,o]     = reaction . W_pred[o,:] + b_pred[o]
// ---------------------------------------------------------------------------
__global__ void __launch_bounds__(256) pool_kernel(
    const float* __restrict__ r_feats, const float* __restrict__ p_feats,
    const float* __restrict__ r_new,   const float* __restrict__ p_new,
    const float* __restrict__ W_pred,  const float* __restrict__ b_pred,
    float* __restrict__ d_out)
{
    const int b = blockIdx.x;
    const int t = threadIdx.x;
    __shared__ float sw[16];
    __shared__ float sRed[OUTD][8];
    if (t < 16) sw[t] = g_w[(t >> 3) * BATCH * MOL + b * MOL + (t & 7)];
    __syncthreads();

    float part[OUTD] = {0.f, 0.f, 0.f, 0.f};
    for (int d0 = 0; d0 < DIM; d0 += 256) {
        int d = d0 + t;
        float acc = 0.f;
#pragma unroll
        for (int m = 0; m < MOL; m++) {
            size_t off = ((size_t)m * BATCH + b) * DIM + d;
            acc += sw[m]     * (r_feats[off] + r_new[off]);
            acc -= sw[8 + m] * (p_feats[off] + p_new[off]);
        }
#pragma unroll
        for (int o = 0; o < OUTD; o++) part[o] += acc * W_pred[o * DIM + d];
    }

    int lane = t & 31, wid = t >> 5;
#pragma unroll
    for (int o = 0; o < OUTD; o++) {
        float v = part[o];
#pragma unroll
        for (int off = 16; off > 0; off >>= 1)
            v += __shfl_down_sync(0xFFFFFFFFu, v, off);
        if (lane == 0) sRed[o][wid] = v;
    }
    __syncthreads();
    if (t < OUTD) {
        float s = 0.f;
#pragma unroll
        for (int w = 0; w < 8; w++) s += sRed[t][w];
        d_out[b * OUTD + t] = s + b_pred[t];
    }
}

// ---------------------------------------------------------------------------
extern "C" void kernel_launch(void* const* d_in, const int* in_sizes, int n_in,
                              void* d_out, int out_size) {
    const float* r_feats = (const float*)d_in[0];
    const float* p_feats = (const float*)d_in[1];
    const float* r_new   = (const float*)d_in[2];
    const float* p_new   = (const float*)d_in[3];
    const float* Wq      = (const float*)d_in[4];
    const float* Wk      = (const float*)d_in[5];
    const float* W_pred  = (const float*)d_in[6];
    const float* b_pred  = (const float*)d_in[7];
    float* out = (float*)d_out;

    // 1) WkT
    transpose_kernel<<<dim3(32, 32), dim3(32, 8)>>>(Wk);
    // 2) G = Wq @ Wk^T   (1024x1024x1024)
    gemm_kernel<<<dim3(8, 8), 256>>>(Wq, 0, nullptr, nullptr);
    // 3) Z = [P;R] @ G   (32768x1024x1024) — the dominant GEMM
    gemm_kernel<<<dim3(256, 8), 256>>>(nullptr, 1, p_feats, r_feats);
    // 4) grams -> softmax -> att outputs + pooling weights
    att_kernel<<<BATCH, 128>>>(r_feats, p_feats, out);
    // 5) pooling + head
    pool_kernel<<<BATCH, 256>>>(r_feats, p_feats, r_new, p_new, W_pred, b_pred, out);
}

// round 4
// speedup vs baseline: 2.3749x; 2.3749x over previous
#include <cuda_runtime.h>
#include <cuda_bf16.h>
#include <cstdint>

constexpr int BATCH = 2048;
constexpr int DIM   = 1024;
constexpr int MOL   = 8;
constexpr int NPAIR = 28;
constexpr int LQ    = 36;
constexpr int OUTD  = 4;
constexpr int MROWS = 32768;           // 2 * BATCH * MOL

__constant__ int c_pi[NPAIR] = {0,0,0,0,0,0,0,1,1,1,1,1,1,2,2,2,2,2,3,3,3,3,4,4,4,5,5,6};
__constant__ int c_pj[NPAIR] = {1,2,3,4,5,6,7,2,3,4,5,6,7,3,4,5,6,7,4,5,6,7,5,6,7,6,7,7};

// ------------------------- static device scratch ---------------------------
__device__ __nv_bfloat16 g_WqHi[DIM * DIM];
__device__ __nv_bfloat16 g_WqLo[DIM * DIM];
__device__ __nv_bfloat16 g_WkHi[DIM * DIM];
__device__ __nv_bfloat16 g_WkLo[DIM * DIM];
__device__ __nv_bfloat16 g_GtHi[DIM * DIM];          // Gt[n][k] = G[k][n]
__device__ __nv_bfloat16 g_GtLo[DIM * DIM];
__device__ __nv_bfloat16 g_Xhi[(size_t)MROWS * DIM]; // 64 MB, row = s*16384+b*8+m
__device__ __nv_bfloat16 g_Xlo[(size_t)MROWS * DIM]; // 64 MB
__device__ float         g_G[DIM * DIM];             // fp32 Wq @ Wk^T
__device__ float         g_Z[(size_t)MROWS * DIM];   // 128 MB fp32
__device__ float         g_w[2 * BATCH * MOL];

// ------------------------------ helpers ------------------------------------
__device__ __forceinline__ uint32_t s2u(const void* p) {
    uint32_t a;
    asm("{ .reg .u64 t; cvta.to.shared.u64 t, %1; cvt.u32.u64 %0, t; }" : "=r"(a) : "l"(p));
    return a;
}
__device__ __forceinline__ void cpa16(uint32_t d, const void* g) {
    asm volatile("cp.async.cg.shared.global [%0], [%1], 16;" :: "r"(d), "l"(g));
}
#define CP_COMMIT()  asm volatile("cp.async.commit_group;" ::: "memory")
#define CP_WAIT1()   asm volatile("cp.async.wait_group 1;" ::: "memory")
#define CP_WAIT0()   asm volatile("cp.async.wait_group 0;" ::: "memory")

__device__ __forceinline__ void lda4(uint32_t* f, uint32_t mbase, int wm, int mt,
                                     int ks, int lane) {
    int g = lane >> 3, r = lane & 7;
    int mloc = wm + mt * 16 + (g & 1) * 8 + r;
    int kloc = ks * 16 + (g >> 1) * 8;
    uint32_t a = mbase + (mloc * 40 + kloc) * 2;
    asm volatile("ldmatrix.sync.aligned.m8n8.x4.shared.b16 {%0,%1,%2,%3}, [%4];"
        : "=r"(f[0]), "=r"(f[1]), "=r"(f[2]), "=r"(f[3]) : "r"(a));
}
__device__ __forceinline__ void ldb2(uint32_t* f, uint32_t mbase, int wn, int nt,
                                     int ks, int lane) {
    int l = lane & 15;
    int g = l >> 3, r = l & 7;
    int nloc = wn + nt * 8 + r;
    int kloc = ks * 16 + g * 8;
    uint32_t a = mbase + (nloc * 40 + kloc) * 2;
    asm volatile("ldmatrix.sync.aligned.m8n8.x2.shared.b16 {%0,%1}, [%2];"
        : "=r"(f[0]), "=r"(f[1]) : "r"(a));
}
__device__ __forceinline__ void mma16816(float* c, const uint32_t* a, const uint32_t* b) {
    asm volatile("mma.sync.aligned.m16n8k16.row.col.f32.bf16.bf16.f32 "
        "{%0,%1,%2,%3}, {%4,%5,%6,%7}, {%8,%9}, {%0,%1,%2,%3};"
        : "+f"(c[0]), "+f"(c[1]), "+f"(c[2]), "+f"(c[3])
        : "r"(a[0]), "r"(a[1]), "r"(a[2]), "r"(a[3]), "r"(b[0]), "r"(b[1]));
}

// ------------------------- split kernels -----------------------------------
__global__ void __launch_bounds__(256) split_w(const float* __restrict__ Wq,
                                               const float* __restrict__ Wk) {
    int bx = blockIdx.x;
    int mat = bx >> 10;                   // 0 = Wq, 1 = Wk
    int row = bx & 1023;
    const float* src = (mat ? Wk : Wq) + (size_t)row * DIM;
    __nv_bfloat16* hi = (mat ? g_WkHi : g_WqHi) + (size_t)row * DIM;
    __nv_bfloat16* lo = (mat ? g_WkLo : g_WqLo) + (size_t)row * DIM;
    int t = threadIdx.x;
#pragma unroll
    for (int i = 0; i < 4; i++) {
        int c = t * 4 + i;
        float v = src[c];
        __nv_bfloat16 h = __float2bfloat16_rn(v);
        hi[c] = h;
        lo[c] = __float2bfloat16_rn(v - __bfloat162float(h));
    }
}

// X split-gather: row = s*16384 + b*8 + m -> feats[m, b, :]
__global__ void __launch_bounds__(256) split_x(const float* __restrict__ p,
                                               const float* __restrict__ r) {
    int row = blockIdx.x;
    int s = row >> 14, b = (row >> 3) & (BATCH - 1), m = row & 7;
    const float* src = (s ? r : p) + ((size_t)m * BATCH + b) * DIM;
    __nv_bfloat16* hi = g_Xhi + (size_t)row * DIM;
    __nv_bfloat16* lo = g_Xlo + (size_t)row * DIM;
    int t = threadIdx.x;
    float4 v = ((const float4*)src)[t];
    float vv[4] = {v.x, v.y, v.z, v.w};
#pragma unroll
    for (int i = 0; i < 4; i++) {
        __nv_bfloat16 h = __float2bfloat16_rn(vv[i]);
        hi[t * 4 + i] = h;
        lo[t * 4 + i] = __float2bfloat16_rn(vv[i] - __bfloat162float(h));
    }
}

// transpose fp32 G -> bf16 hi/lo Gt (Gt[n][k] = G[k][n])
__global__ void tsplit_g() {
    __shared__ float tile[32][33];
    int tx = threadIdx.x, ty = threadIdx.y;
    int x = blockIdx.x * 32 + tx;       // n
    int y0 = blockIdx.y * 32;           // k
#pragma unroll
    for (int i = ty; i < 32; i += 8)
        tile[i][tx] = g_G[(size_t)(y0 + i) * DIM + x];
    __syncthreads();
    int k2 = y0 + tx;
#pragma unroll
    for (int i = ty; i < 32; i += 8) {
        float v = tile[tx][i];
        __nv_bfloat16 h = __float2bfloat16_rn(v);
        size_t o = (size_t)(blockIdx.x * 32 + i) * DIM + k2;
        g_GtHi[o] = h;
        g_GtLo[o] = __float2bfloat16_rn(v - __bfloat162float(h));
    }
}

// ------------------------- mma.sync split GEMM -----------------------------
// C[M,1024] fp32 = Ahi@B^T terms: Ahi*Bhi + Alo*Bhi + Ahi*Blo
// A: [M,1024] bf16 row-major; B: [1024,1024] bf16 K-major ([n][k])
// CTA tile 128x128, K-chunk 32, 2-stage cp.async; 8 warps of 64x32.
// Smem row stride 40 bf16 (80 B) -> conflict-free ldmatrix.
constexpr int MAT_ELE  = 128 * 40;              // 5120 bf16 per matrix tile
constexpr int STAGE_B  = 4 * MAT_ELE * 2;       // 40960 bytes per stage
constexpr int SMEM_GEMM = 2 * STAGE_B;          // 81920 bytes

__device__ __forceinline__ void load_chunk(
    uint32_t sbase, int stage,
    const __nv_bfloat16* __restrict__ Ahi, const __nv_bfloat16* __restrict__ Alo,
    const __nv_bfloat16* __restrict__ Bhi, const __nv_bfloat16* __restrict__ Blo,
    int rowBase, int colBase, int k0, int tid)
{
    uint32_t st = sbase + stage * STAGE_B;
#pragma unroll
    for (int mat = 0; mat < 4; mat++) {
        const __nv_bfloat16* src0 =
            (mat == 0) ? Ahi : (mat == 1) ? Alo : (mat == 2) ? Bhi : Blo;
        int base = (mat < 2) ? rowBase : colBase;
#pragma unroll
        for (int h = 0; h < 2; h++) {
            int idx = h * 256 + tid;          // 0..511
            int row = idx >> 2, ch = idx & 3; // 128 rows x 4 chunks of 16B
            const __nv_bfloat16* src = src0 + (size_t)(base + row) * DIM + k0 + ch * 8;
            uint32_t dst = st + (mat * MAT_ELE + row * 40 + ch * 8) * 2;
            cpa16(dst, src);
        }
    }
    CP_COMMIT();
}

__global__ void __launch_bounds__(256) mma_gemm(
    const __nv_bfloat16* __restrict__ Ahi, const __nv_bfloat16* __restrict__ Alo,
    const __nv_bfloat16* __restrict__ Bhi, const __nv_bfloat16* __restrict__ Blo,
    float* __restrict__ C)
{
    extern __shared__ char smem[];
    uint32_t sbase = s2u(smem);
    const int tid  = threadIdx.x;
    const int lane = tid & 31;
    const int wid  = tid >> 5;
    const int wm = (wid >> 2) * 64;     // warp row offset (2 rows of warps)
    const int wn = (wid & 3) * 32;      // warp col offset (4 cols of warps)
    const int rowBase = blockIdx.x * 128;
    const int colBase = blockIdx.y * 128;

    float acc[4][4][4];
#pragma unroll
    for (int i = 0; i < 4; i++)
#pragma unroll
        for (int j = 0; j < 4; j++)
#pragma unroll
            for (int q = 0; q < 4; q++) acc[i][j][q] = 0.f;

    load_chunk(sbase, 0, Ahi, Alo, Bhi, Blo, rowBase, colBase, 0, tid);

    for (int c = 0; c < 32; ++c) {
        int s = c & 1;
        if (c < 31) {
            load_chunk(sbase, s ^ 1, Ahi, Alo, Bhi, Blo, rowBase, colBase,
                       (c + 1) * 32, tid);
            CP_WAIT1();
        } else {
            CP_WAIT0();
        }
        __syncthreads();

        uint32_t stb = sbase + s * STAGE_B;
        uint32_t bAhi = stb;
        uint32_t bAlo = stb + MAT_ELE * 2;
        uint32_t bBhi = stb + 2 * MAT_ELE * 2;
        uint32_t bBlo = stb + 3 * MAT_ELE * 2;

#pragma unroll
        for (int ks = 0; ks < 2; ks++) {
            uint32_t ahif[4][4], alof[4][4], bhif[4][2], blof[4][2];
#pragma unroll
            for (int mt = 0; mt < 4; mt++) {
                lda4(ahif[mt], bAhi, wm, mt, ks, lane);
                lda4(alof[mt], bAlo, wm, mt, ks, lane);
            }
#pragma unroll
            for (int nt = 0; nt < 4; nt++) {
                ldb2(bhif[nt], bBhi, wn, nt, ks, lane);
                ldb2(blof[nt], bBlo, wn, nt, ks, lane);
            }
#pragma unroll
            for (int mt = 0; mt < 4; mt++)
#pragma unroll
                for (int nt = 0; nt < 4; nt++) {
                    mma16816(acc[mt][nt], ahif[mt], bhif[nt]);
                    mma16816(acc[mt][nt], alof[mt], bhif[nt]);
                    mma16816(acc[mt][nt], ahif[mt], blof[nt]);
                }
        }
        __syncthreads();
    }

    // epilogue
#pragma unroll
    for (int mt = 0; mt < 4; mt++) {
        int r0 = rowBase + wm + mt * 16 + (lane >> 2);
#pragma unroll
        for (int nt = 0; nt < 4; nt++) {
            int col = colBase + wn + nt * 8 + (lane & 3) * 2;
            float2 v0 = make_float2(acc[mt][nt][0], acc[mt][nt][1]);
            float2 v1 = make_float2(acc[mt][nt][2], acc[mt][nt][3]);
            *(float2*)&C[(size_t)r0 * DIM + col]       = v0;
            *(float2*)&C[(size_t)(r0 + 8) * DIM + col] = v1;
        }
    }
}

// ------------------------- attention (smem-staged) -------------------------
__global__ void __launch_bounds__(128) att_kernel(
    const float* __restrict__ r_feats, const float* __restrict__ p_feats,
    float* __restrict__ d_out)
{
    const int b = blockIdx.x;
    const int t = threadIdx.x;

    __shared__ float zb[16][132];
    __shared__ float fb[16][132];
    __shared__ float sS[2][MOL][MOL];
    __shared__ float sProb[2][LQ][LQ];
    __shared__ float sAtt[2][LQ];

    const int side = t >> 6, q = (t >> 3) & 7, k = t & 7;
    float acc = 0.f;

    for (int d0 = 0; d0 < DIM; d0 += 128) {
        __syncthreads();
#pragma unroll
        for (int pass = 0; pass < 4; pass++) {
            int row = pass * 4 + (t >> 5);
            int j = (t & 31) * 4;
            int sd = row >> 3, idx = row & 7;
            const float* zsrc = g_Z + (((size_t)sd * BATCH + b) * MOL + idx) * DIM + d0 + j;
            const float* fbase = sd ? p_feats : r_feats;
            const float* fsrc = fbase + ((size_t)idx * BATCH + b) * DIM + d0 + j;
            *(float4*)&zb[row][j] = *(const float4*)zsrc;
            *(float4*)&fb[row][j] = *(const float4*)fsrc;
        }
        __syncthreads();
        const float* zr = zb[side * 8 + q];
        const float* fr = fb[side * 8 + k];
#pragma unroll
        for (int d = 0; d < 128; d += 4) {
            float4 zv = *(const float4*)(zr + d);
            float4 fv = *(const float4*)(fr + d);
            acc += zv.x * fv.x + zv.y * fv.y + zv.z * fv.z + zv.w * fv.w;
        }
    }
    sS[side][q][k] = acc;
    __syncthreads();

    if (t < 2 * LQ) {
        int sd = t / LQ, qq = t % LQ;
        int qi, qj;
        if (qq < MOL) { qi = qq; qj = -1; }
        else          { qi = c_pi[qq - MOL]; qj = c_pj[qq - MOL]; }
        float row[LQ];
        float maxv = -1e30f;
#pragma unroll
        for (int kk = 0; kk < LQ; kk++) {
            int ki, kj;
            if (kk < MOL) { ki = kk; kj = -1; }
            else          { ki = c_pi[kk - MOL]; kj = c_pj[kk - MOL]; }
            float v = sS[sd][qi][ki];
            if (kj >= 0) v += sS[sd][qi][kj];
            if (qj >= 0) {
                v += sS[sd][qj][ki];
                if (kj >= 0) v += sS[sd][qj][kj];
            }
            v *= 0.03125f;
            row[kk] = v;
            maxv = fmaxf(maxv, v);
        }
        float sum = 0.f;
#pragma unroll
        for (int kk = 0; kk < LQ; kk++) { row[kk] = expf(row[kk] - maxv); sum += row[kk]; }
        float inv = 1.f / sum;
#pragma unroll
        for (int kk = 0; kk < LQ; kk++) sProb[sd][qq][kk] = row[kk] * inv;
    }
    __syncthreads();

    if (t < 2 * LQ) {
        int sd = t / LQ, kk = t % LQ;
        float a = 0.f;
#pragma unroll
        for (int qq = 0; qq < LQ; qq++) a += sProb[sd][qq][kk];
        a *= (1.0f / LQ);
        sAtt[sd][kk] = a;
        d_out[BATCH * OUTD + sd * (BATCH * LQ) + b * LQ + kk] = a;
    }
    __syncthreads();

    if (t < 16) {
        int sd = t >> 3, m = t & 7;
        float w = sAtt[sd][m];
#pragma unroll
        for (int pp = 0; pp < NPAIR; pp++)
            if (c_pi[pp] == m || c_pj[pp] == m) w += sAtt[sd][MOL + pp];
        g_w[sd * BATCH * MOL + b * MOL + m] = w;
    }
}

// ------------------------- pooling + head ----------------------------------
__global__ void __launch_bounds__(256) pool_kernel(
    const float* __restrict__ r_feats, const float* __restrict__ p_feats,
    const float* __restrict__ r_new,   const float* __restrict__ p_new,
    const float* __restrict__ W_pred,  const float* __restrict__ b_pred,
    float* __restrict__ d_out)
{
    const int b = blockIdx.x;
    const int t = threadIdx.x;
    __shared__ float sw[16];
    __shared__ float sRed[OUTD][8];
    if (t < 16) sw[t] = g_w[(t >> 3) * BATCH * MOL + b * MOL + (t & 7)];
    __syncthreads();

    float part[OUTD] = {0.f, 0.f, 0.f, 0.f};
    for (int d0 = 0; d0 < DIM; d0 += 256) {
        int d = d0 + t;
        float acc = 0.f;
#pragma unroll
        for (int m = 0; m < MOL; m++) {
            size_t off = ((size_t)m * BATCH + b) * DIM + d;
            acc += sw[m]     * (r_feats[off] + r_new[off]);
            acc -= sw[8 + m] * (p_feats[off] + p_new[off]);
        }
#pragma unroll
        for (int o = 0; o < OUTD; o++) part[o] += acc * W_pred[o * DIM + d];
    }
    int lane = t & 31, wid = t >> 5;
#pragma unroll
    for (int o = 0; o < OUTD; o++) {
        float v = part[o];
#pragma unroll
        for (int off = 16; off > 0; off >>= 1)
            v += __shfl_down_sync(0xFFFFFFFFu, v, off);
        if (lane == 0) sRed[o][wid] = v;
    }
    __syncthreads();
    if (t < OUTD) {
        float s = 0.f;
#pragma unroll
        for (int w = 0; w < 8; w++) s += sRed[t][w];
        d_out[b * OUTD + t] = s + b_pred[t];
    }
}

// ---------------------------------------------------------------------------
extern "C" void kernel_launch(void* const* d_in, const int* in_sizes, int n_in,
                              void* d_out, int out_size) {
    const float* r_feats = (const float*)d_in[0];
    const float* p_feats = (const float*)d_in[1];
    const float* r_new   = (const float*)d_in[2];
    const float* p_new   = (const float*)d_in[3];
    const float* Wq      = (const float*)d_in[4];
    const float* Wk      = (const float*)d_in[5];
    const float* W_pred  = (const float*)d_in[6];
    const float* b_pred  = (const float*)d_in[7];
    float* out = (float*)d_out;

    cudaFuncSetAttribute(mma_gemm, cudaFuncAttributeMaxDynamicSharedMemorySize,
                         SMEM_GEMM);

    __nv_bfloat16 *WqHi, *WqLo, *WkHi, *WkLo, *GtHi, *GtLo, *Xhi, *Xlo;
    float *G, *Z;
    cudaGetSymbolAddress((void**)&WqHi, g_WqHi);
    cudaGetSymbolAddress((void**)&WqLo, g_WqLo);
    cudaGetSymbolAddress((void**)&WkHi, g_WkHi);
    cudaGetSymbolAddress((void**)&WkLo, g_WkLo);
    cudaGetSymbolAddress((void**)&GtHi, g_GtHi);
    cudaGetSymbolAddress((void**)&GtLo, g_GtLo);
    cudaGetSymbolAddress((void**)&Xhi,  g_Xhi);
    cudaGetSymbolAddress((void**)&Xlo,  g_Xlo);
    cudaGetSymbolAddress((void**)&G,    g_G);
    cudaGetSymbolAddress((void**)&Z,    g_Z);

    // 1) weight splits
    split_w<<<2048, 256>>>(Wq, Wk);
    // 2) G = Wq @ Wk^T (Wk rows are already [N,K] K-major)
    mma_gemm<<<dim3(8, 8), 256, SMEM_GEMM>>>(WqHi, WqLo, WkHi, WkLo, G);
    // 3) transpose+split G -> Gt for use as B in the main GEMM
    tsplit_g<<<dim3(32, 32), dim3(32, 8)>>>();
    // 4) gather+split X
    split_x<<<MROWS, 256>>>(p_feats, r_feats);
    // 5) Z = X @ G  (dominant GEMM)
    mma_gemm<<<dim3(256, 8), 256, SMEM_GEMM>>>(Xhi, Xlo, GtHi, GtLo, Z);
    // 6) grams -> softmax -> att outputs + pooling weights
    att_kernel<<<BATCH, 128>>>(r_feats, p_feats, out);
    // 7) pooling + head
    pool_kernel<<<BATCH, 256>>>(r_feats, p_feats, r_new, p_new, W_pred, b_pred, out);
}